// round 11
// baseline (speedup 1.0000x reference)
#include <cuda_runtime.h>
#include <cuda_bf16.h>
#include <math.h>

#define NB 4
#define NT 100
#define ND 256
#define NHW 256
#define NF 400
#define BN_EPS 1e-5f

// ---------------- scratch (device globals; no allocations) ----------------
__device__ float g_y[NF * ND * NHW];     // conv output [f][oc][hw]  (~100MB)
__device__ unsigned int g_Apack[589824]; // packed bf16 hi/lo weight fragments (2.36MB)
__device__ float g_scale[ND], g_shift[ND];
__device__ float g_ctx[NF * ND];
__device__ float g_G1[NF * 4 * ND];
__device__ float g_Weff[4 * ND * ND];
__device__ float g_hx[NB * ND];
__device__ float g_cx[NB * ND];
__device__ float g_hist[NT * NB * ND];

// ======================= weight fragment pre-pack ==========================
// Apack idx = (((s*9+tap)*16 + icb)*16 + mt)*128 + lane*4 + j
// j: 0:(oc=g,   k=2q)  1:(oc=g+8, k=2q)  2:(oc=g, k=2q+8)  3:(oc=g+8, k=2q+8)
// word packs {split_s(W[oc][ic]), split_s(W[oc][ic+1])} (low half = even ic)
__global__ void __launch_bounds__(256) aprep_kernel(const float* __restrict__ w) {
    int idx = blockIdx.x * 256 + threadIdx.x;
    if (idx >= 589824) return;
    int j    = idx & 3;
    int lane = (idx >> 2) & 31;
    int mt   = (idx >> 7) & 15;
    int icb  = (idx >> 11) & 15;
    int rest = idx >> 15;            // s*9 + tap
    int tap  = rest % 9, s = rest / 9;
    int g = lane >> 2, q4 = lane & 3;
    int oc = mt * 16 + g + (j & 1) * 8;
    int qq = q4 + (j >> 1) * 4;
    int ic = icb * 16 + qq * 2;
    float w0 = w[((size_t)oc * 256 + ic) * 9 + tap];
    float w1 = w[((size_t)oc * 256 + ic + 1) * 9 + tap];
    __nv_bfloat162 v;
    if (s == 0) {
        v.x = __float2bfloat16(w0);
        v.y = __float2bfloat16(w1);
    } else {
        v.x = __float2bfloat16(w0 - __bfloat162float(__float2bfloat16(w0)));
        v.y = __float2bfloat16(w1 - __bfloat162float(__float2bfloat16(w1)));
    }
    g_Apack[idx] = *(unsigned int*)&v;
}

// ======================= conv as implicit GEMM (bf16x3 mma) ================
// Per frame: O[256 oc][256 hw] = W[256][2304] * P[2304][256], K = tap-major.
// CTA = (frame, oc-QUARTER of 64).  8 warps: (warp>>2) in {0,1} -> 32-oc
// group, (warp&3) -> 64-hw group.  Warp tile 32oc x 64hw -> acc = 64 regs
// (prev 64x64 tile = 128 acc regs overflowed 255 and spilled -> 3.8ms conv).
#define MMA16816(d, a0_, a1_, a2_, a3_, b0_, b1_)                               \
    asm volatile(                                                               \
        "mma.sync.aligned.m16n8k16.row.col.f32.bf16.bf16.f32 "                  \
        "{%0,%1,%2,%3},{%4,%5,%6,%7},{%8,%9},{%0,%1,%2,%3};"                    \
        : "+f"(d[0]), "+f"(d[1]), "+f"(d[2]), "+f"(d[3])                        \
        : "r"(a0_), "r"(a1_), "r"(a2_), "r"(a3_), "r"(b0_), "r"(b1_))

__global__ void __launch_bounds__(256, 1) convmma_kernel(const float* __restrict__ x,
                                                         const float* __restrict__ bias) {
    __shared__ unsigned int bp[2][2][8][324];   // [buf][hi/lo][ic-pair][pix]

    int f    = blockIdx.x >> 2;
    int quar = blockIdx.x & 3;
    int tid  = threadIdx.x;
    int lane = tid & 31, warp = tid >> 5;
    int g = lane >> 2, q4 = lane & 3;
    int ocg = warp >> 2;               // 0..1
    int hww = (warp & 3) * 64;

    const float* xf = x + (size_t)f * 65536;

    // zero the borders of all plane buffers (stays zero; staging writes interior only)
    for (int i = tid; i < 324; i += 256) {
        int r = i / 18, c = i % 18;
        if (r == 0 || r == 17 || c == 0 || c == 17) {
#pragma unroll
            for (int bu = 0; bu < 2; bu++)
#pragma unroll
                for (int s = 0; s < 2; s++)
#pragma unroll
                    for (int p = 0; p < 8; p++) bp[bu][s][p][i] = 0u;
        }
    }

    float acc[2][8][4];
#pragma unroll
    for (int mt = 0; mt < 2; mt++)
#pragma unroll
        for (int nt = 0; nt < 8; nt++)
#pragma unroll
            for (int r = 0; r < 4; r++) acc[mt][nt][r] = 0.f;

    int sp = warp;          // staging: ic-pair handled by this warp
    // stage chunk 0 into buf 0
    {
        const float* x0p = xf + (0 * 16 + sp * 2) * 256;
#pragma unroll
        for (int j = 0; j < 8; j++) {
            int px = lane + j * 32;
            float v0 = x0p[px], v1 = x0p[256 + px];
            __nv_bfloat162 h, l;
            h.x = __float2bfloat16(v0); h.y = __float2bfloat16(v1);
            l.x = __float2bfloat16(v0 - __bfloat162float(h.x));
            l.y = __float2bfloat16(v1 - __bfloat162float(h.y));
            int pix = (px >> 4) * 18 + (px & 15) + 19;
            bp[0][0][sp][pix] = *(unsigned int*)&h;
            bp[0][1][sp][pix] = *(unsigned int*)&l;
        }
    }
    __syncthreads();

    // pixel-base per n-tile (row, col within 16x16)
    int rowb[8], colb[8];
#pragma unroll
    for (int nt = 0; nt < 8; nt++) {
        int n0 = hww + nt * 8;
        rowb[nt] = n0 >> 4;
        colb[nt] = n0 & 15;
    }

    for (int ch = 0; ch < 16; ch++) {
        int buf = ch & 1;
        if (ch < 15) {      // prefetch-stage next chunk into other buffer
            const float* x0p = xf + ((ch + 1) * 16 + sp * 2) * 256;
#pragma unroll
            for (int j = 0; j < 8; j++) {
                int px = lane + j * 32;
                float v0 = x0p[px], v1 = x0p[256 + px];
                __nv_bfloat162 h, l;
                h.x = __float2bfloat16(v0); h.y = __float2bfloat16(v1);
                l.x = __float2bfloat16(v0 - __bfloat162float(h.x));
                l.y = __float2bfloat16(v1 - __bfloat162float(h.y));
                int pix = (px >> 4) * 18 + (px & 15) + 19;
                bp[buf ^ 1][0][sp][pix] = *(unsigned int*)&h;
                bp[buf ^ 1][1][sp][pix] = *(unsigned int*)&l;
            }
        }

        for (int tap = 0; tap < 9; tap++) {
            int dh = tap / 3, dw = tap % 3;
            // ---- B fragments: one LDS.32 each ----
            unsigned int bh0[8], bh1[8], bl0[8], bl1[8];
#pragma unroll
            for (int nt = 0; nt < 8; nt++) {
                int pix = (rowb[nt] + dh) * 18 + colb[nt] + dw + g;
                bh0[nt] = bp[buf][0][q4][pix];
                bh1[nt] = bp[buf][0][q4 + 4][pix];
                bl0[nt] = bp[buf][1][q4][pix];
                bl1[nt] = bp[buf][1][q4 + 4][pix];
            }
            // ---- A fragments: LDG.128, L2-hot ----
            uint4 ah[2], al[2];
#pragma unroll
            for (int mt = 0; mt < 2; mt++) {
                int mtg = quar * 4 + ocg * 2 + mt;
                ah[mt] = *(const uint4*)&g_Apack[(((0 * 9 + tap) * 16 + ch) * 16 + mtg) * 128 + lane * 4];
                al[mt] = *(const uint4*)&g_Apack[(((1 * 9 + tap) * 16 + ch) * 16 + mtg) * 128 + lane * 4];
            }
            // ---- 48 MMAs: Wh*Xh + Wh*Xl + Wl*Xh ----
#pragma unroll
            for (int mt = 0; mt < 2; mt++) {
#pragma unroll
                for (int nt = 0; nt < 8; nt++) {
                    MMA16816(acc[mt][nt], ah[mt].x, ah[mt].y, ah[mt].z, ah[mt].w, bh0[nt], bh1[nt]);
                    MMA16816(acc[mt][nt], ah[mt].x, ah[mt].y, ah[mt].z, ah[mt].w, bl0[nt], bl1[nt]);
                    MMA16816(acc[mt][nt], al[mt].x, al[mt].y, al[mt].z, al[mt].w, bh0[nt], bh1[nt]);
                }
            }
        }
        __syncthreads();
    }

    // ---- epilogue: bias + store fp32 [oc][hw] ----
    float* yout = g_y + (size_t)f * 65536;
#pragma unroll
    for (int mt = 0; mt < 2; mt++) {
        int oc = quar * 64 + ocg * 32 + mt * 16 + g;
        float b0v = bias[oc], b8v = bias[oc + 8];
#pragma unroll
        for (int nt = 0; nt < 8; nt++) {
            int hw = hww + nt * 8 + q4 * 2;
            float2 lo = make_float2(acc[mt][nt][0] + b0v, acc[mt][nt][1] + b0v);
            float2 hi = make_float2(acc[mt][nt][2] + b8v, acc[mt][nt][3] + b8v);
            *(float2*)&yout[oc * 256 + hw] = lo;
            *(float2*)&yout[(oc + 8) * 256 + hw] = hi;
        }
    }
}

// ---------------- BN stats -> scale/shift per channel (double accum) -------
__global__ void __launch_bounds__(256) stats_kernel(const float* __restrict__ gamma,
                                                    const float* __restrict__ beta) {
    int c = blockIdx.x, tid = threadIdx.x;
    double s = 0.0, ss = 0.0;
    for (int i = tid; i < NF * 256; i += 256) {
        int f = i >> 8, d = i & 255;
        double v = (double)g_y[(size_t)f * 65536 + c * 256 + d];
        s += v;
        ss += v * v;
    }
    __shared__ double rs[256], rss[256];
    rs[tid] = s; rss[tid] = ss;
    __syncthreads();
    for (int st = 128; st > 0; st >>= 1) {
        if (tid < st) { rs[tid] += rs[tid + st]; rss[tid] += rss[tid + st]; }
        __syncthreads();
    }
    if (tid == 0) {
        double n = (double)(NF * 256);
        double mu = rs[0] / n;
        double var = rss[0] / n - mu * mu;
        double rstd = 1.0 / sqrt(var + (double)BN_EPS);
        g_scale[c] = (float)((double)gamma[c] * rstd);
        g_shift[c] = (float)((double)beta[c] - mu * (double)gamma[c] * rstd);
    }
}

// ---------------- attention: alphas, alpha_logps (hx-independent!) + ctx_f ----
__global__ void __launch_bounds__(256) attn_kernel(const float* __restrict__ wattn,
                                                   float* __restrict__ out) {
    int f = blockIdx.x, tid = threadIdx.x;
    int b = f / NT, t = f % NT;
    __shared__ __align__(16) float sc_s[256], sh_s[256], wa_s[256], alpha_s[256];
    __shared__ float wred[8];
    __shared__ float red[2];

    sc_s[tid] = g_scale[tid];
    sh_s[tid] = g_shift[tid];
    wa_s[tid] = wattn[tid];
    __syncthreads();

    const float4* y4 = (const float4*)(g_y + (size_t)f * 65536 + tid * 256);
    const float4* wa4 = (const float4*)wa_s;
    float scl = sc_s[tid], shl = sh_s[tid];
    float s = 0.f;
#pragma unroll 8
    for (int d4 = 0; d4 < 64; d4++) {
        float4 y = y4[d4], wa = wa4[d4];
        s += fmaxf(fmaf(y.x, scl, shl), 0.f) * wa.x;
        s += fmaxf(fmaf(y.y, scl, shl), 0.f) * wa.y;
        s += fmaxf(fmaf(y.z, scl, shl), 0.f) * wa.z;
        s += fmaxf(fmaf(y.w, scl, shl), 0.f) * wa.w;
    }

    float m = s;
#pragma unroll
    for (int o = 16; o; o >>= 1) m = fmaxf(m, __shfl_xor_sync(0xffffffffu, m, o));
    if ((tid & 31) == 0) wred[tid >> 5] = m;
    __syncthreads();
    if (tid == 0) {
        float mm = wred[0];
        for (int i = 1; i < 8; i++) mm = fmaxf(mm, wred[i]);
        red[0] = mm;
    }
    __syncthreads();
    float M = red[0];
    float e = expf(s - M);
    float z = e;
#pragma unroll
    for (int o = 16; o; o >>= 1) z += __shfl_xor_sync(0xffffffffu, z, o);
    if ((tid & 31) == 0) wred[tid >> 5] = z;
    __syncthreads();
    if (tid == 0) {
        float zz = 0.f;
        for (int i = 0; i < 8; i++) zz += wred[i];
        red[1] = zz;
    }
    __syncthreads();
    float Z = red[1];
    float alpha = e / Z;
    float lp = s - M - logf(Z);

    int oidx = (t * NB + b) * 256 + tid;
    out[800 + oidx] = alpha;
    out[103200 + oidx] = lp;
    alpha_s[tid] = alpha;
    __syncthreads();

    const float* yf = g_y + (size_t)f * 65536;
    float acc = 0.f;
    for (int l = 0; l < 256; l++) {
        float v = yf[l * 256 + tid];
        acc += fmaxf(fmaf(v, sc_s[l], sh_s[l]), 0.f) * alpha_s[l];
    }
    g_ctx[f * 256 + tid] = acc;
}

// ---------------- initial hx/cx (coalesced warp-per-dot) ----------------
__global__ void __launch_bounds__(256) init_kernel(const float* __restrict__ ihw,
                                                   const float* __restrict__ ihb,
                                                   const float* __restrict__ icw,
                                                   const float* __restrict__ icb) {
    int b = blockIdx.x, tid = threadIdx.x;
    int lane = tid & 31, warp = tid >> 5;
    __shared__ float x0[256], sc_s[256], sh_s[256];
    sc_s[tid] = g_scale[tid];
    sh_s[tid] = g_shift[tid];
    __syncthreads();
    const float* yf = g_y + (size_t)(b * NT) * 65536;
    float s = 0.f;
    for (int l = 0; l < 256; l++)
        s += fmaxf(fmaf(yf[l * 256 + tid], sc_s[l], sh_s[l]), 0.f);
    x0[tid] = s * (1.f / 256.f);
    __syncthreads();
    for (int d0 = warp; d0 < 512; d0 += 8) {
        int j = d0 & 255, which = d0 >> 8;
        const float* wr = (which ? icw : ihw) + (size_t)j * 256;
        float a = 0.f;
        for (int k = lane; k < 256; k += 32) a += wr[k] * x0[k];
#pragma unroll
        for (int o = 16; o; o >>= 1) a += __shfl_xor_sync(0xffffffffu, a, o);
        if (lane == 0) {
            if (which) g_cx[b * 256 + j] = tanhf(a + icb[j]);
            else       g_hx[b * 256 + j] = tanhf(a + ihb[j]);
        }
    }
}

// ---------------- Weff = Wih @ w_w + Whh  (1024x256) ----------------
__global__ void __launch_bounds__(256) weff_kernel(const float* __restrict__ wih,
                                                   const float* __restrict__ ww,
                                                   const float* __restrict__ whh) {
    int j0 = blockIdx.x * 4, tid = threadIdx.x;
    __shared__ float wr[4][256];
    for (int i = tid; i < 1024; i += 256)
        wr[i >> 8][i & 255] = wih[(j0 + (i >> 8)) * 256 + (i & 255)];
    __syncthreads();
    float a0 = whh[(j0 + 0) * 256 + tid];
    float a1 = whh[(j0 + 1) * 256 + tid];
    float a2 = whh[(j0 + 2) * 256 + tid];
    float a3 = whh[(j0 + 3) * 256 + tid];
    for (int d = 0; d < 256; d++) {
        float wv = ww[d * 256 + tid];
        a0 += wr[0][d] * wv;
        a1 += wr[1][d] * wv;
        a2 += wr[2][d] * wv;
        a3 += wr[3][d] * wv;
    }
    g_Weff[(j0 + 0) * 256 + tid] = a0;
    g_Weff[(j0 + 1) * 256 + tid] = a1;
    g_Weff[(j0 + 2) * 256 + tid] = a2;
    g_Weff[(j0 + 3) * 256 + tid] = a3;
}

// ---------------- G1 = (ctx_f + w_b) @ Wih^T + bih + bhh ----------------
__global__ void __launch_bounds__(1024) g1_kernel(const float* __restrict__ wih,
                                                  const float* __restrict__ wb,
                                                  const float* __restrict__ bih,
                                                  const float* __restrict__ bhh) {
    int f = blockIdx.x, j = threadIdx.x;
    __shared__ __align__(16) float cv[256];
    if (j < 256) cv[j] = g_ctx[f * 256 + j] + wb[j];
    __syncthreads();
    float a = bih[j] + bhh[j];
    const float4* w4 = (const float4*)(wih + (size_t)j * 256);
    const float4* c4 = (const float4*)cv;
#pragma unroll 8
    for (int d4 = 0; d4 < 64; d4++) {
        float4 w = w4[d4], c = c4[d4];
        a += w.x * c.x + w.y * c.y + w.z * c.z + w.w * c.w;
    }
    g_G1[f * 1024 + j] = a;
}

// ---------------- LSTM step: gates = G1[t] + hx @ Weff^T (per-t launch) ----
__global__ void __launch_bounds__(1024) step_kernel(int t) {
    int b = blockIdx.x;
    int j = threadIdx.x;
    __shared__ __align__(16) float hx_s[256];
    __shared__ float gsm[1024];

    if (j < 256) hx_s[j] = g_hx[b * 256 + j];
    __syncthreads();

    float a = g_G1[(b * NT + t) * 1024 + j];
    const float4* w4 = (const float4*)(g_Weff + (size_t)j * 256);
    const float4* h4 = (const float4*)hx_s;
#pragma unroll 8
    for (int k4 = 0; k4 < 64; k4++) {
        float4 w = w4[k4], h = h4[k4];
        a += w.x * h.x + w.y * h.y + w.z * h.z + w.w * h.w;
    }
    gsm[j] = a;
    __syncthreads();

    if (j < 256) {
        int r = j;
        float gi = gsm[r], gf = gsm[256 + r], gg = gsm[512 + r], go = gsm[768 + r];
        float si = 1.f / (1.f + expf(-gi));
        float sf = 1.f / (1.f + expf(-gf));
        float so = 1.f / (1.f + expf(-go));
        float c = sf * g_cx[b * 256 + r] + si * tanhf(gg);
        g_cx[b * 256 + r] = c;
        float h = so * tanhf(c);
        g_hx[b * 256 + r] = h;
        g_hist[t * 1024 + b * 256 + r] = h;
    }
}

// ---------------- preds[t,b,e] = hx_t @ wout^T + b ----------------
__global__ void __launch_bounds__(256) preds_kernel(const float* __restrict__ woutw,
                                                    const float* __restrict__ woutb,
                                                    float* __restrict__ out) {
    int t = blockIdx.x, tid = threadIdx.x;
    int pair = tid >> 5, lane = tid & 31;
    if (pair >= 8) return;
    int b = pair >> 1, e = pair & 1;
    const float* hrow = g_hist + t * 1024 + b * 256;
    const float* wr = woutw + e * 256;
    float s = 0.f;
    for (int k = lane; k < 256; k += 32) s += hrow[k] * wr[k];
#pragma unroll
    for (int o = 16; o; o >>= 1) s += __shfl_xor_sync(0xffffffffu, s, o);
    if (lane == 0) out[(t * 4 + b) * 2 + e] = s + woutb[e];
}

// ---------------- launch ----------------
extern "C" void kernel_launch(void* const* d_in, const int* in_sizes, int n_in,
                              void* d_out, int out_size) {
    const float* cam    = (const float*)d_in[0];
    const float* convw  = (const float*)d_in[1];
    const float* convb  = (const float*)d_in[2];
    const float* gamma  = (const float*)d_in[3];
    const float* beta   = (const float*)d_in[4];
    const float* ihw    = (const float*)d_in[5];
    const float* ihb    = (const float*)d_in[6];
    const float* icw    = (const float*)d_in[7];
    const float* icb    = (const float*)d_in[8];
    const float* ww     = (const float*)d_in[9];
    const float* wb     = (const float*)d_in[10];
    const float* wattnw = (const float*)d_in[11];
    // d_in[12] = wattn_b : drops out of softmax/log_softmax (shift-invariant)
    const float* wih    = (const float*)d_in[13];
    const float* whh    = (const float*)d_in[14];
    const float* bih    = (const float*)d_in[15];
    const float* bhh    = (const float*)d_in[16];
    const float* woutw  = (const float*)d_in[17];
    const float* woutb  = (const float*)d_in[18];
    float* out = (float*)d_out;

    aprep_kernel<<<2304, 256>>>(convw);
    convmma_kernel<<<NF * 4, 256>>>(cam, convb);
    stats_kernel<<<ND, 256>>>(gamma, beta);
    attn_kernel<<<NF, 256>>>(wattnw, out);
    init_kernel<<<NB, 256>>>(ihw, ihb, icw, icb);
    weff_kernel<<<ND, 256>>>(wih, ww, whh);
    g1_kernel<<<NF, 1024>>>(wih, wb, bih, bhh);
    for (int t = 0; t < NT; t++)
        step_kernel<<<NB, 1024>>>(t);
    preds_kernel<<<NT, 256>>>(woutw, woutb, out);
}

// round 12
// speedup vs baseline: 1.0443x; 1.0443x over previous
#include <cuda_runtime.h>
#include <cuda_bf16.h>
#include <math.h>

#define NB 4
#define NT 100
#define ND 256
#define NHW 256
#define NF 400
#define BN_EPS 1e-5f

// ---------------- scratch (device globals; no allocations) ----------------
__device__ float g_y[NF * ND * NHW];     // conv output [f][oc][hw]  (~100MB)
__device__ unsigned int g_Apack[589824]; // packed bf16 hi/lo weight fragments (2.36MB)
__device__ float g_scale[ND], g_shift[ND];
__device__ float g_ctx[NF * ND];
__device__ float g_G1[NF * 4 * ND];
__device__ float g_Weff[4 * ND * ND];
__device__ float g_hx[NB * ND];
__device__ float g_cx[NB * ND];
__device__ float g_hist[NT * NB * ND];

// ======================= weight fragment pre-pack ==========================
// Apack idx = (((s*9+tap)*16 + icb)*16 + mt)*128 + lane*4 + j
// j: 0:(oc=g,   k=2q)  1:(oc=g+8, k=2q)  2:(oc=g, k=2q+8)  3:(oc=g+8, k=2q+8)
// word packs {split_s(W[oc][ic]), split_s(W[oc][ic+1])} (low half = even ic)
__global__ void __launch_bounds__(256) aprep_kernel(const float* __restrict__ w) {
    int idx = blockIdx.x * 256 + threadIdx.x;
    if (idx >= 589824) return;
    int j    = idx & 3;
    int lane = (idx >> 2) & 31;
    int mt   = (idx >> 7) & 15;
    int icb  = (idx >> 11) & 15;
    int rest = idx >> 15;            // s*9 + tap
    int tap  = rest % 9, s = rest / 9;
    int g = lane >> 2, q4 = lane & 3;
    int oc = mt * 16 + g + (j & 1) * 8;
    int qq = q4 + (j >> 1) * 4;
    int ic = icb * 16 + qq * 2;
    float w0 = w[((size_t)oc * 256 + ic) * 9 + tap];
    float w1 = w[((size_t)oc * 256 + ic + 1) * 9 + tap];
    __nv_bfloat162 v;
    if (s == 0) {
        v.x = __float2bfloat16(w0);
        v.y = __float2bfloat16(w1);
    } else {
        v.x = __float2bfloat16(w0 - __bfloat162float(__float2bfloat16(w0)));
        v.y = __float2bfloat16(w1 - __bfloat162float(__float2bfloat16(w1)));
    }
    g_Apack[idx] = *(unsigned int*)&v;
}

// ======================= conv as implicit GEMM (bf16x3 mma) ================
// Per frame: O[256 oc][256 hw] = W[256][2304] * P[2304][256], K = tap-major.
// CTA = (frame, oc-QUARTER of 64).  8 warps: (warp>>2) in {0,1} -> 32-oc
// group, (warp&3) -> 64-hw group.  Warp tile 32oc x 64hw -> acc = 64 regs
// (prev 64x64 tile = 128 acc regs overflowed 255 and spilled -> 3.8ms conv).
#define MMA16816(d, a0_, a1_, a2_, a3_, b0_, b1_)                               \
    asm volatile(                                                               \
        "mma.sync.aligned.m16n8k16.row.col.f32.bf16.bf16.f32 "                  \
        "{%0,%1,%2,%3},{%4,%5,%6,%7},{%8,%9},{%0,%1,%2,%3};"                    \
        : "+f"(d[0]), "+f"(d[1]), "+f"(d[2]), "+f"(d[3])                        \
        : "r"(a0_), "r"(a1_), "r"(a2_), "r"(a3_), "r"(b0_), "r"(b1_))

__global__ void __launch_bounds__(256, 1) convmma_kernel(const float* __restrict__ x,
                                                         const float* __restrict__ bias) {
    __shared__ unsigned int bp[2][2][8][324];   // [buf][hi/lo][ic-pair][pix]

    int f    = blockIdx.x >> 2;
    int quar = blockIdx.x & 3;
    int tid  = threadIdx.x;
    int lane = tid & 31, warp = tid >> 5;
    int g = lane >> 2, q4 = lane & 3;
    int ocg = warp >> 2;               // 0..1
    int hww = (warp & 3) * 64;

    const float* xf = x + (size_t)f * 65536;

    // zero the borders of all plane buffers (stays zero; staging writes interior only)
    for (int i = tid; i < 324; i += 256) {
        int r = i / 18, c = i % 18;
        if (r == 0 || r == 17 || c == 0 || c == 17) {
#pragma unroll
            for (int bu = 0; bu < 2; bu++)
#pragma unroll
                for (int s = 0; s < 2; s++)
#pragma unroll
                    for (int p = 0; p < 8; p++) bp[bu][s][p][i] = 0u;
        }
    }

    float acc[2][8][4];
#pragma unroll
    for (int mt = 0; mt < 2; mt++)
#pragma unroll
        for (int nt = 0; nt < 8; nt++)
#pragma unroll
            for (int r = 0; r < 4; r++) acc[mt][nt][r] = 0.f;

    int sp = warp;          // staging: ic-pair handled by this warp
    // stage chunk 0 into buf 0
    {
        const float* x0p = xf + (0 * 16 + sp * 2) * 256;
#pragma unroll
        for (int j = 0; j < 8; j++) {
            int px = lane + j * 32;
            float v0 = x0p[px], v1 = x0p[256 + px];
            __nv_bfloat162 h, l;
            h.x = __float2bfloat16(v0); h.y = __float2bfloat16(v1);
            l.x = __float2bfloat16(v0 - __bfloat162float(h.x));
            l.y = __float2bfloat16(v1 - __bfloat162float(h.y));
            int pix = (px >> 4) * 18 + (px & 15) + 19;
            bp[0][0][sp][pix] = *(unsigned int*)&h;
            bp[0][1][sp][pix] = *(unsigned int*)&l;
        }
    }
    __syncthreads();

    // pixel-base per n-tile (row, col within 16x16)
    int rowb[8], colb[8];
#pragma unroll
    for (int nt = 0; nt < 8; nt++) {
        int n0 = hww + nt * 8;
        rowb[nt] = n0 >> 4;
        colb[nt] = n0 & 15;
    }

    for (int ch = 0; ch < 16; ch++) {
        int buf = ch & 1;
        if (ch < 15) {      // prefetch-stage next chunk into other buffer
            const float* x0p = xf + ((ch + 1) * 16 + sp * 2) * 256;
#pragma unroll
            for (int j = 0; j < 8; j++) {
                int px = lane + j * 32;
                float v0 = x0p[px], v1 = x0p[256 + px];
                __nv_bfloat162 h, l;
                h.x = __float2bfloat16(v0); h.y = __float2bfloat16(v1);
                l.x = __float2bfloat16(v0 - __bfloat162float(h.x));
                l.y = __float2bfloat16(v1 - __bfloat162float(h.y));
                int pix = (px >> 4) * 18 + (px & 15) + 19;
                bp[buf ^ 1][0][sp][pix] = *(unsigned int*)&h;
                bp[buf ^ 1][1][sp][pix] = *(unsigned int*)&l;
            }
        }

        for (int tap = 0; tap < 9; tap++) {
            int dh = tap / 3, dw = tap % 3;
            // ---- B fragments: one LDS.32 each ----
            unsigned int bh0[8], bh1[8], bl0[8], bl1[8];
#pragma unroll
            for (int nt = 0; nt < 8; nt++) {
                int pix = (rowb[nt] + dh) * 18 + colb[nt] + dw + g;
                bh0[nt] = bp[buf][0][q4][pix];
                bh1[nt] = bp[buf][0][q4 + 4][pix];
                bl0[nt] = bp[buf][1][q4][pix];
                bl1[nt] = bp[buf][1][q4 + 4][pix];
            }
            // ---- A fragments: LDG.128, L2-hot ----
            uint4 ah[2], al[2];
#pragma unroll
            for (int mt = 0; mt < 2; mt++) {
                int mtg = quar * 4 + ocg * 2 + mt;
                ah[mt] = *(const uint4*)&g_Apack[(((0 * 9 + tap) * 16 + ch) * 16 + mtg) * 128 + lane * 4];
                al[mt] = *(const uint4*)&g_Apack[(((1 * 9 + tap) * 16 + ch) * 16 + mtg) * 128 + lane * 4];
            }
            // ---- 48 MMAs: Wh*Xh + Wh*Xl + Wl*Xh ----
#pragma unroll
            for (int mt = 0; mt < 2; mt++) {
#pragma unroll
                for (int nt = 0; nt < 8; nt++) {
                    MMA16816(acc[mt][nt], ah[mt].x, ah[mt].y, ah[mt].z, ah[mt].w, bh0[nt], bh1[nt]);
                    MMA16816(acc[mt][nt], ah[mt].x, ah[mt].y, ah[mt].z, ah[mt].w, bl0[nt], bl1[nt]);
                    MMA16816(acc[mt][nt], al[mt].x, al[mt].y, al[mt].z, al[mt].w, bh0[nt], bh1[nt]);
                }
            }
        }
        __syncthreads();
    }

    // ---- epilogue: bias + store fp32 [oc][hw] ----
    float* yout = g_y + (size_t)f * 65536;
#pragma unroll
    for (int mt = 0; mt < 2; mt++) {
        int oc = quar * 64 + ocg * 32 + mt * 16 + g;
        float b0v = bias[oc], b8v = bias[oc + 8];
#pragma unroll
        for (int nt = 0; nt < 8; nt++) {
            int hw = hww + nt * 8 + q4 * 2;
            float2 lo = make_float2(acc[mt][nt][0] + b0v, acc[mt][nt][1] + b0v);
            float2 hi = make_float2(acc[mt][nt][2] + b8v, acc[mt][nt][3] + b8v);
            *(float2*)&yout[oc * 256 + hw] = lo;
            *(float2*)&yout[(oc + 8) * 256 + hw] = hi;
        }
    }
}

// ---------------- BN stats -> scale/shift per channel (double accum) -------
__global__ void __launch_bounds__(256) stats_kernel(const float* __restrict__ gamma,
                                                    const float* __restrict__ beta) {
    int c = blockIdx.x, tid = threadIdx.x;
    double s = 0.0, ss = 0.0;
    for (int i = tid; i < NF * 256; i += 256) {
        int f = i >> 8, d = i & 255;
        double v = (double)g_y[(size_t)f * 65536 + c * 256 + d];
        s += v;
        ss += v * v;
    }
    __shared__ double rs[256], rss[256];
    rs[tid] = s; rss[tid] = ss;
    __syncthreads();
    for (int st = 128; st > 0; st >>= 1) {
        if (tid < st) { rs[tid] += rs[tid + st]; rss[tid] += rss[tid + st]; }
        __syncthreads();
    }
    if (tid == 0) {
        double n = (double)(NF * 256);
        double mu = rs[0] / n;
        double var = rss[0] / n - mu * mu;
        double rstd = 1.0 / sqrt(var + (double)BN_EPS);
        g_scale[c] = (float)((double)gamma[c] * rstd);
        g_shift[c] = (float)((double)beta[c] - mu * (double)gamma[c] * rstd);
    }
}

// ---------------- attention: alphas, alpha_logps (hx-independent!) + ctx_f ----
__global__ void __launch_bounds__(256) attn_kernel(const float* __restrict__ wattn,
                                                   float* __restrict__ out) {
    int f = blockIdx.x, tid = threadIdx.x;
    int b = f / NT, t = f % NT;
    __shared__ __align__(16) float sc_s[256], sh_s[256], wa_s[256], alpha_s[256];
    __shared__ float wred[8];
    __shared__ float red[2];

    sc_s[tid] = g_scale[tid];
    sh_s[tid] = g_shift[tid];
    wa_s[tid] = wattn[tid];
    __syncthreads();

    const float4* y4 = (const float4*)(g_y + (size_t)f * 65536 + tid * 256);
    const float4* wa4 = (const float4*)wa_s;
    float scl = sc_s[tid], shl = sh_s[tid];
    float s = 0.f;
#pragma unroll 8
    for (int d4 = 0; d4 < 64; d4++) {
        float4 y = y4[d4], wa = wa4[d4];
        s += fmaxf(fmaf(y.x, scl, shl), 0.f) * wa.x;
        s += fmaxf(fmaf(y.y, scl, shl), 0.f) * wa.y;
        s += fmaxf(fmaf(y.z, scl, shl), 0.f) * wa.z;
        s += fmaxf(fmaf(y.w, scl, shl), 0.f) * wa.w;
    }

    float m = s;
#pragma unroll
    for (int o = 16; o; o >>= 1) m = fmaxf(m, __shfl_xor_sync(0xffffffffu, m, o));
    if ((tid & 31) == 0) wred[tid >> 5] = m;
    __syncthreads();
    if (tid == 0) {
        float mm = wred[0];
        for (int i = 1; i < 8; i++) mm = fmaxf(mm, wred[i]);
        red[0] = mm;
    }
    __syncthreads();
    float M = red[0];
    float e = expf(s - M);
    float z = e;
#pragma unroll
    for (int o = 16; o; o >>= 1) z += __shfl_xor_sync(0xffffffffu, z, o);
    if ((tid & 31) == 0) wred[tid >> 5] = z;
    __syncthreads();
    if (tid == 0) {
        float zz = 0.f;
        for (int i = 0; i < 8; i++) zz += wred[i];
        red[1] = zz;
    }
    __syncthreads();
    float Z = red[1];
    float alpha = e / Z;
    float lp = s - M - logf(Z);

    int oidx = (t * NB + b) * 256 + tid;
    out[800 + oidx] = alpha;
    out[103200 + oidx] = lp;
    alpha_s[tid] = alpha;
    __syncthreads();

    const float* yf = g_y + (size_t)f * 65536;
    float acc = 0.f;
    for (int l = 0; l < 256; l++) {
        float v = yf[l * 256 + tid];
        acc += fmaxf(fmaf(v, sc_s[l], sh_s[l]), 0.f) * alpha_s[l];
    }
    g_ctx[f * 256 + tid] = acc;
}

// ---------------- initial hx/cx (coalesced warp-per-dot) ----------------
__global__ void __launch_bounds__(256) init_kernel(const float* __restrict__ ihw,
                                                   const float* __restrict__ ihb,
                                                   const float* __restrict__ icw,
                                                   const float* __restrict__ icb) {
    int b = blockIdx.x, tid = threadIdx.x;
    int lane = tid & 31, warp = tid >> 5;
    __shared__ float x0[256], sc_s[256], sh_s[256];
    sc_s[tid] = g_scale[tid];
    sh_s[tid] = g_shift[tid];
    __syncthreads();
    const float* yf = g_y + (size_t)(b * NT) * 65536;
    float s = 0.f;
    for (int l = 0; l < 256; l++)
        s += fmaxf(fmaf(yf[l * 256 + tid], sc_s[l], sh_s[l]), 0.f);
    x0[tid] = s * (1.f / 256.f);
    __syncthreads();
    for (int d0 = warp; d0 < 512; d0 += 8) {
        int j = d0 & 255, which = d0 >> 8;
        const float* wr = (which ? icw : ihw) + (size_t)j * 256;
        float a = 0.f;
        for (int k = lane; k < 256; k += 32) a += wr[k] * x0[k];
#pragma unroll
        for (int o = 16; o; o >>= 1) a += __shfl_xor_sync(0xffffffffu, a, o);
        if (lane == 0) {
            if (which) g_cx[b * 256 + j] = tanhf(a + icb[j]);
            else       g_hx[b * 256 + j] = tanhf(a + ihb[j]);
        }
    }
}

// ---------------- Weff = Wih @ w_w + Whh  (1024x256) ----------------
__global__ void __launch_bounds__(256) weff_kernel(const float* __restrict__ wih,
                                                   const float* __restrict__ ww,
                                                   const float* __restrict__ whh) {
    int j0 = blockIdx.x * 4, tid = threadIdx.x;
    __shared__ float wr[4][256];
    for (int i = tid; i < 1024; i += 256)
        wr[i >> 8][i & 255] = wih[(j0 + (i >> 8)) * 256 + (i & 255)];
    __syncthreads();
    float a0 = whh[(j0 + 0) * 256 + tid];
    float a1 = whh[(j0 + 1) * 256 + tid];
    float a2 = whh[(j0 + 2) * 256 + tid];
    float a3 = whh[(j0 + 3) * 256 + tid];
    for (int d = 0; d < 256; d++) {
        float wv = ww[d * 256 + tid];
        a0 += wr[0][d] * wv;
        a1 += wr[1][d] * wv;
        a2 += wr[2][d] * wv;
        a3 += wr[3][d] * wv;
    }
    g_Weff[(j0 + 0) * 256 + tid] = a0;
    g_Weff[(j0 + 1) * 256 + tid] = a1;
    g_Weff[(j0 + 2) * 256 + tid] = a2;
    g_Weff[(j0 + 3) * 256 + tid] = a3;
}

// ---------------- G1 = (ctx_f + w_b) @ Wih^T + bih + bhh ----------------
__global__ void __launch_bounds__(1024) g1_kernel(const float* __restrict__ wih,
                                                  const float* __restrict__ wb,
                                                  const float* __restrict__ bih,
                                                  const float* __restrict__ bhh) {
    int f = blockIdx.x, j = threadIdx.x;
    __shared__ __align__(16) float cv[256];
    if (j < 256) cv[j] = g_ctx[f * 256 + j] + wb[j];
    __syncthreads();
    float a = bih[j] + bhh[j];
    const float4* w4 = (const float4*)(wih + (size_t)j * 256);
    const float4* c4 = (const float4*)cv;
#pragma unroll 8
    for (int d4 = 0; d4 < 64; d4++) {
        float4 w = w4[d4], c = c4[d4];
        a += w.x * c.x + w.y * c.y + w.z * c.z + w.w * c.w;
    }
    g_G1[f * 1024 + j] = a;
}

// ---------------- LSTM step: gates = G1[t] + hx @ Weff^T (per-t launch) ----
__global__ void __launch_bounds__(1024) step_kernel(int t) {
    int b = blockIdx.x;
    int j = threadIdx.x;
    __shared__ __align__(16) float hx_s[256];
    __shared__ float gsm[1024];

    if (j < 256) hx_s[j] = g_hx[b * 256 + j];
    __syncthreads();

    float a = g_G1[(b * NT + t) * 1024 + j];
    const float4* w4 = (const float4*)(g_Weff + (size_t)j * 256);
    const float4* h4 = (const float4*)hx_s;
#pragma unroll 8
    for (int k4 = 0; k4 < 64; k4++) {
        float4 w = w4[k4], h = h4[k4];
        a += w.x * h.x + w.y * h.y + w.z * h.z + w.w * h.w;
    }
    gsm[j] = a;
    __syncthreads();

    if (j < 256) {
        int r = j;
        float gi = gsm[r], gf = gsm[256 + r], gg = gsm[512 + r], go = gsm[768 + r];
        float si = 1.f / (1.f + expf(-gi));
        float sf = 1.f / (1.f + expf(-gf));
        float so = 1.f / (1.f + expf(-go));
        float c = sf * g_cx[b * 256 + r] + si * tanhf(gg);
        g_cx[b * 256 + r] = c;
        float h = so * tanhf(c);
        g_hx[b * 256 + r] = h;
        g_hist[t * 1024 + b * 256 + r] = h;
    }
}

// ---------------- preds[t,b,e] = hx_t @ wout^T + b ----------------
__global__ void __launch_bounds__(256) preds_kernel(const float* __restrict__ woutw,
                                                    const float* __restrict__ woutb,
                                                    float* __restrict__ out) {
    int t = blockIdx.x, tid = threadIdx.x;
    int pair = tid >> 5, lane = tid & 31;
    if (pair >= 8) return;
    int b = pair >> 1, e = pair & 1;
    const float* hrow = g_hist + t * 1024 + b * 256;
    const float* wr = woutw + e * 256;
    float s = 0.f;
    for (int k = lane; k < 256; k += 32) s += hrow[k] * wr[k];
#pragma unroll
    for (int o = 16; o; o >>= 1) s += __shfl_xor_sync(0xffffffffu, s, o);
    if (lane == 0) out[(t * 4 + b) * 2 + e] = s + woutb[e];
}

// ---------------- launch ----------------
extern "C" void kernel_launch(void* const* d_in, const int* in_sizes, int n_in,
                              void* d_out, int out_size) {
    const float* cam    = (const float*)d_in[0];
    const float* convw  = (const float*)d_in[1];
    const float* convb  = (const float*)d_in[2];
    const float* gamma  = (const float*)d_in[3];
    const float* beta   = (const float*)d_in[4];
    const float* ihw    = (const float*)d_in[5];
    const float* ihb    = (const float*)d_in[6];
    const float* icw    = (const float*)d_in[7];
    const float* icb    = (const float*)d_in[8];
    const float* ww     = (const float*)d_in[9];
    const float* wb     = (const float*)d_in[10];
    const float* wattnw = (const float*)d_in[11];
    // d_in[12] = wattn_b : drops out of softmax/log_softmax (shift-invariant)
    const float* wih    = (const float*)d_in[13];
    const float* whh    = (const float*)d_in[14];
    const float* bih    = (const float*)d_in[15];
    const float* bhh    = (const float*)d_in[16];
    const float* woutw  = (const float*)d_in[17];
    const float* woutb  = (const float*)d_in[18];
    float* out = (float*)d_out;

    aprep_kernel<<<2304, 256>>>(convw);
    convmma_kernel<<<NF * 4, 256>>>(cam, convb);
    stats_kernel<<<ND, 256>>>(gamma, beta);
    attn_kernel<<<NF, 256>>>(wattnw, out);
    init_kernel<<<NB, 256>>>(ihw, ihb, icw, icb);
    weff_kernel<<<ND, 256>>>(wih, ww, whh);
    g1_kernel<<<NF, 1024>>>(wih, wb, bih, bhh);
    for (int t = 0; t < NT; t++)
        step_kernel<<<NB, 1024>>>(t);
    preds_kernel<<<NT, 256>>>(woutw, woutb, out);
}

// round 15
// speedup vs baseline: 1.1578x; 1.1087x over previous
#include <cuda_runtime.h>
#include <cuda_fp16.h>
#include <cstdint>
#include <math.h>

#define NB 4
#define NT 100
#define ND 256
#define NHW 256
#define NF 400
#define BN_EPS 1e-5f

// ---------------- scratch (device globals; no allocations) ----------------
__device__ float g_y[NF * ND * NHW];     // conv output [f][oc][hw]  (~100MB)
__device__ unsigned int g_Apack[294912]; // packed fp16 weight fragments (1.18MB)
__device__ float g_scale[ND], g_shift[ND];
__device__ float g_ctx[NF * ND];
__device__ float g_G1[NF * 4 * ND];
__device__ float g_Weff[4 * ND * ND];
__device__ float g_hx[NB * ND];
__device__ float g_cx[NB * ND];
__device__ float g_hist[NT * NB * ND];

// ======================= weight fragment pre-pack (fp16) ===================
// Apack idx = ((tap*16 + icb)*16 + mt)*128 + lane*4 + j
// j: 0:(oc=g, k=2q) 1:(oc=g+8, k=2q) 2:(oc=g, k=2q+8) 3:(oc=g+8, k=2q+8)
// word packs {W[oc][ic], W[oc][ic+1]} as fp16x2 (low half = even ic)
__global__ void __launch_bounds__(256) aprep_kernel(const float* __restrict__ w) {
    int idx = blockIdx.x * 256 + threadIdx.x;
    if (idx >= 294912) return;
    int j    = idx & 3;
    int lane = (idx >> 2) & 31;
    int mt   = (idx >> 7) & 15;
    int icb  = (idx >> 11) & 15;
    int tap  = idx >> 15;
    int g = lane >> 2, q4 = lane & 3;
    int oc = mt * 16 + g + (j & 1) * 8;
    int qq = q4 + (j >> 1) * 4;
    int ic = icb * 16 + qq * 2;
    float w0 = w[((size_t)oc * 256 + ic) * 9 + tap];
    float w1 = w[((size_t)oc * 256 + ic + 1) * 9 + tap];
    __half2 v;
    v.x = __float2half(w0);
    v.y = __float2half(w1);
    g_Apack[idx] = *(unsigned int*)&v;
}

// ======================= conv as implicit GEMM (fp16 single-pass) ==========
// Per frame: O[256 oc][256 hw] = W[256][2304] * P[2304][256], K = tap-major.
// CTA = (frame, oc-QUARTER of 64). 8 warps: ocg=(warp>>2), hw-tile=(warp&3).
// Warp tile 32oc x 64hw, 16 MMAs/tap. Single fp16 pass: 144 HMMA/tileset
// (vs 432 for the 3-term bf16 split) — fallback-HMMA instr-rate bound.
#define MMA16816(d, a0_, a1_, a2_, a3_, b0_, b1_)                               \
    asm volatile(                                                               \
        "mma.sync.aligned.m16n8k16.row.col.f32.f16.f16.f32 "                    \
        "{%0,%1,%2,%3},{%4,%5,%6,%7},{%8,%9},{%0,%1,%2,%3};"                    \
        : "+f"(d[0]), "+f"(d[1]), "+f"(d[2]), "+f"(d[3])                        \
        : "r"(a0_), "r"(a1_), "r"(a2_), "r"(a3_), "r"(b0_), "r"(b1_))

__global__ void __launch_bounds__(256) convmma_kernel(const float* __restrict__ x,
                                                      const float* __restrict__ bias) {
    __shared__ unsigned int bp[2][8][324];   // [buf][ic-pair][pix], fp16x2

    int f    = blockIdx.x >> 2;
    int quar = blockIdx.x & 3;
    int tid  = threadIdx.x;
    int lane = tid & 31, warp = tid >> 5;
    int g = lane >> 2, q4 = lane & 3;
    int ocg = warp >> 2;               // 0..1
    int hww = (warp & 3) * 64;

    const float* xf = x + (size_t)f * 65536;

    // zero borders of both plane buffers (staging writes interior only)
    for (int i = tid; i < 324; i += 256) {
        int r = i / 18, c = i % 18;
        if (r == 0 || r == 17 || c == 0 || c == 17) {
            bp[0][0][i] = 0u; bp[0][1][i] = 0u; bp[0][2][i] = 0u; bp[0][3][i] = 0u;
            bp[0][4][i] = 0u; bp[0][5][i] = 0u; bp[0][6][i] = 0u; bp[0][7][i] = 0u;
            bp[1][0][i] = 0u; bp[1][1][i] = 0u; bp[1][2][i] = 0u; bp[1][3][i] = 0u;
            bp[1][4][i] = 0u; bp[1][5][i] = 0u; bp[1][6][i] = 0u; bp[1][7][i] = 0u;
        }
    }

    float acc[2][8][4];
#pragma unroll
    for (int mt = 0; mt < 2; mt++)
#pragma unroll
        for (int nt = 0; nt < 8; nt++)
#pragma unroll
            for (int r = 0; r < 4; r++) acc[mt][nt][r] = 0.f;

    int sp = warp;          // staging: ic-pair handled by this warp
    {
        const float* x0p = xf + (sp * 2) * 256;
#pragma unroll
        for (int j = 0; j < 8; j++) {
            int px = lane + j * 32;
            __half2 h;
            h.x = __float2half(x0p[px]);
            h.y = __float2half(x0p[256 + px]);
            int pix = (px >> 4) * 18 + (px & 15) + 19;
            bp[0][sp][pix] = *(unsigned int*)&h;
        }
    }
    __syncthreads();

    int rowb[8], colb[8];
#pragma unroll
    for (int nt = 0; nt < 8; nt++) {
        int n0 = hww + nt * 8;
        rowb[nt] = n0 >> 4;
        colb[nt] = n0 & 15;
    }

    for (int ch = 0; ch < 16; ch++) {
        int buf = ch & 1;
        if (ch < 15) {      // prefetch-stage next chunk into other buffer
            const float* x0p = xf + ((ch + 1) * 16 + sp * 2) * 256;
#pragma unroll
            for (int j = 0; j < 8; j++) {
                int px = lane + j * 32;
                __half2 h;
                h.x = __float2half(x0p[px]);
                h.y = __float2half(x0p[256 + px]);
                int pix = (px >> 4) * 18 + (px & 15) + 19;
                bp[buf ^ 1][sp][pix] = *(unsigned int*)&h;
            }
        }

        for (int tap = 0; tap < 9; tap++) {
            int dh = tap / 3, dw = tap % 3;
            unsigned int bh0[8], bh1[8];
#pragma unroll
            for (int nt = 0; nt < 8; nt++) {
                int pix = (rowb[nt] + dh) * 18 + colb[nt] + dw + g;
                bh0[nt] = bp[buf][q4][pix];
                bh1[nt] = bp[buf][q4 + 4][pix];
            }
            uint4 ah[2];
#pragma unroll
            for (int mt = 0; mt < 2; mt++) {
                int mtg = quar * 4 + ocg * 2 + mt;
                ah[mt] = *(const uint4*)&g_Apack[((tap * 16 + ch) * 16 + mtg) * 128 + lane * 4];
            }
#pragma unroll
            for (int mt = 0; mt < 2; mt++)
#pragma unroll
                for (int nt = 0; nt < 8; nt++)
                    MMA16816(acc[mt][nt], ah[mt].x, ah[mt].y, ah[mt].z, ah[mt].w,
                             bh0[nt], bh1[nt]);
        }
        __syncthreads();
    }

    // ---- epilogue: bias + store fp32 [oc][hw] ----
    float* yout = g_y + (size_t)f * 65536;
#pragma unroll
    for (int mt = 0; mt < 2; mt++) {
        int oc = quar * 64 + ocg * 32 + mt * 16 + g;
        float b0v = bias[oc], b8v = bias[oc + 8];
#pragma unroll
        for (int nt = 0; nt < 8; nt++) {
            int hw = hww + nt * 8 + q4 * 2;
            float2 lo = make_float2(acc[mt][nt][0] + b0v, acc[mt][nt][1] + b0v);
            float2 hi = make_float2(acc[mt][nt][2] + b8v, acc[mt][nt][3] + b8v);
            *(float2*)&yout[oc * 256 + hw] = lo;
            *(float2*)&yout[(oc + 8) * 256 + hw] = hi;
        }
    }
}

// ---------------- BN stats -> scale/shift per channel (double accum) -------
__global__ void __launch_bounds__(256) stats_kernel(const float* __restrict__ gamma,
                                                    const float* __restrict__ beta) {
    int c = blockIdx.x, tid = threadIdx.x;
    double s = 0.0, ss = 0.0;
    for (int i = tid; i < NF * 256; i += 256) {
        double v = (double)g_y[(size_t)(i >> 8) * 65536 + c * 256 + (i & 255)];
        s += v; ss += v * v;
    }
    __shared__ double rs[256], rss[256];
    rs[tid] = s; rss[tid] = ss;
    __syncthreads();
    for (int st = 128; st > 0; st >>= 1) {
        if (tid < st) { rs[tid] += rs[tid + st]; rss[tid] += rss[tid + st]; }
        __syncthreads();
    }
    if (tid == 0) {
        double n = (double)(NF * 256);
        double mu = rs[0] / n;
        double var = rss[0] / n - mu * mu;
        double rstd = 1.0 / sqrt(var + (double)BN_EPS);
        g_scale[c] = (float)((double)gamma[c] * rstd);
        g_shift[c] = (float)((double)beta[c] - mu * (double)gamma[c] * rstd);
    }
}

// ---------------- attention: alphas, alpha_logps (hx-independent!) + ctx_f ----
__global__ void __launch_bounds__(256) attn_kernel(const float* __restrict__ wattn,
                                                   float* __restrict__ out) {
    int f = blockIdx.x, tid = threadIdx.x;
    int b = f / NT, t = f % NT;
    __shared__ __align__(16) float sc_s[256], sh_s[256], wa_s[256], alpha_s[256];
    __shared__ float wred[8], red[2];

    sc_s[tid] = g_scale[tid];
    sh_s[tid] = g_shift[tid];
    wa_s[tid] = wattn[tid];
    __syncthreads();

    const float4* y4 = (const float4*)(g_y + (size_t)f * 65536 + tid * 256);
    const float4* wa4 = (const float4*)wa_s;
    float scl = sc_s[tid], shl = sh_s[tid], s = 0.f;
#pragma unroll 8
    for (int d4 = 0; d4 < 64; d4++) {
        float4 y = y4[d4], wa = wa4[d4];
        s += fmaxf(fmaf(y.x, scl, shl), 0.f) * wa.x;
        s += fmaxf(fmaf(y.y, scl, shl), 0.f) * wa.y;
        s += fmaxf(fmaf(y.z, scl, shl), 0.f) * wa.z;
        s += fmaxf(fmaf(y.w, scl, shl), 0.f) * wa.w;
    }

    float m = s;
#pragma unroll
    for (int o = 16; o; o >>= 1) m = fmaxf(m, __shfl_xor_sync(0xffffffffu, m, o));
    if ((tid & 31) == 0) wred[tid >> 5] = m;
    __syncthreads();
    if (tid == 0) {
        float mm = wred[0];
        for (int i = 1; i < 8; i++) mm = fmaxf(mm, wred[i]);
        red[0] = mm;
    }
    __syncthreads();
    float M = red[0];
    float e = expf(s - M);
    float z = e;
#pragma unroll
    for (int o = 16; o; o >>= 1) z += __shfl_xor_sync(0xffffffffu, z, o);
    if ((tid & 31) == 0) wred[tid >> 5] = z;
    __syncthreads();
    if (tid == 0) {
        float zz = 0.f;
        for (int i = 0; i < 8; i++) zz += wred[i];
        red[1] = zz;
    }
    __syncthreads();
    float Z = red[1];
    float alpha = e / Z;
    float lp = s - M - logf(Z);

    int oidx = (t * NB + b) * 256 + tid;
    out[800 + oidx] = alpha;
    out[103200 + oidx] = lp;
    alpha_s[tid] = alpha;
    __syncthreads();

    const float* yf = g_y + (size_t)f * 65536;
    float acc = 0.f;
    for (int l = 0; l < 256; l++) {
        float v = yf[l * 256 + tid];
        acc += fmaxf(fmaf(v, sc_s[l], sh_s[l]), 0.f) * alpha_s[l];
    }
    g_ctx[f * 256 + tid] = acc;
}

// ---------------- initial hx/cx (coalesced warp-per-dot) ----------------
__global__ void __launch_bounds__(256) init_kernel(const float* __restrict__ ihw,
                                                   const float* __restrict__ ihb,
                                                   const float* __restrict__ icw,
                                                   const float* __restrict__ icb) {
    int b = blockIdx.x, tid = threadIdx.x;
    int lane = tid & 31, warp = tid >> 5;
    __shared__ float x0[256], sc_s[256], sh_s[256];
    sc_s[tid] = g_scale[tid];
    sh_s[tid] = g_shift[tid];
    __syncthreads();
    const float* yf = g_y + (size_t)(b * NT) * 65536;
    float s = 0.f;
    for (int l = 0; l < 256; l++)
        s += fmaxf(fmaf(yf[l * 256 + tid], sc_s[l], sh_s[l]), 0.f);
    x0[tid] = s * (1.f / 256.f);
    __syncthreads();
    for (int d0 = warp; d0 < 512; d0 += 8) {
        int j = d0 & 255, which = d0 >> 8;
        const float* wr = (which ? icw : ihw) + (size_t)j * 256;
        float a = 0.f;
        for (int k = lane; k < 256; k += 32) a += wr[k] * x0[k];
#pragma unroll
        for (int o = 16; o; o >>= 1) a += __shfl_xor_sync(0xffffffffu, a, o);
        if (lane == 0) {
            if (which) g_cx[b * 256 + j] = tanhf(a + icb[j]);
            else       g_hx[b * 256 + j] = tanhf(a + ihb[j]);
        }
    }
}

// ---------------- Weff = Wih @ w_w + Whh  (1024x256) ----------------
__global__ void __launch_bounds__(256) weff_kernel(const float* __restrict__ wih,
                                                   const float* __restrict__ ww,
                                                   const float* __restrict__ whh) {
    int j0 = blockIdx.x * 4, tid = threadIdx.x;
    __shared__ float wr[4][256];
    for (int i = tid; i < 1024; i += 256)
        wr[i >> 8][i & 255] = wih[(j0 + (i >> 8)) * 256 + (i & 255)];
    __syncthreads();
    float a0 = whh[(j0 + 0) * 256 + tid], a1 = whh[(j0 + 1) * 256 + tid];
    float a2 = whh[(j0 + 2) * 256 + tid], a3 = whh[(j0 + 3) * 256 + tid];
    for (int d = 0; d < 256; d++) {
        float wv = ww[d * 256 + tid];
        a0 += wr[0][d] * wv; a1 += wr[1][d] * wv;
        a2 += wr[2][d] * wv; a3 += wr[3][d] * wv;
    }
    g_Weff[(j0 + 0) * 256 + tid] = a0;
    g_Weff[(j0 + 1) * 256 + tid] = a1;
    g_Weff[(j0 + 2) * 256 + tid] = a2;
    g_Weff[(j0 + 3) * 256 + tid] = a3;
}

// ---------------- G1 = (ctx_f + w_b) @ Wih^T + bih + bhh ----------------
__global__ void __launch_bounds__(1024) g1_kernel(const float* __restrict__ wih,
                                                  const float* __restrict__ wb,
                                                  const float* __restrict__ bih,
                                                  const float* __restrict__ bhh) {
    int f = blockIdx.x, j = threadIdx.x;
    __shared__ __align__(16) float cv[256];
    if (j < 256) cv[j] = g_ctx[f * 256 + j] + wb[j];
    __syncthreads();
    float a = bih[j] + bhh[j];
    const float4* w4 = (const float4*)(wih + (size_t)j * 256);
    const float4* c4 = (const float4*)cv;
#pragma unroll 8
    for (int d4 = 0; d4 < 64; d4++) {
        float4 w = w4[d4], c = c4[d4];
        a += w.x * c.x + w.y * c.y + w.z * c.z + w.w * c.w;
    }
    g_G1[f * 1024 + j] = a;
}

// ---------------- LSTM step: gates = G1[t] + hx @ Weff^T (per-t launch) ----
__global__ void __launch_bounds__(1024) step_kernel(int t) {
    int b = blockIdx.x, j = threadIdx.x;
    __shared__ __align__(16) float hx_s[256];
    __shared__ float gsm[1024];
    if (j < 256) hx_s[j] = g_hx[b * 256 + j];
    __syncthreads();
    float a = g_G1[(b * NT + t) * 1024 + j];
    const float4* w4 = (const float4*)(g_Weff + (size_t)j * 256);
    const float4* h4 = (const float4*)hx_s;
#pragma unroll 8
    for (int k4 = 0; k4 < 64; k4++) {
        float4 w = w4[k4], hh = h4[k4];
        a += w.x * hh.x + w.y * hh.y + w.z * hh.z + w.w * hh.w;
    }
    gsm[j] = a;
    __syncthreads();
    if (j < 256) {
        float gi = gsm[j], gf = gsm[256 + j], gg = gsm[512 + j], go = gsm[768 + j];
        float si = 1.f / (1.f + expf(-gi));
        float sf = 1.f / (1.f + expf(-gf));
        float so = 1.f / (1.f + expf(-go));
        float c = sf * g_cx[b * 256 + j] + si * tanhf(gg);
        g_cx[b * 256 + j] = c;
        float hv = so * tanhf(c);
        g_hx[b * 256 + j] = hv;
        g_hist[t * 1024 + b * 256 + j] = hv;
    }
}

// ---------------- preds[t,b,e] = hx_t @ wout^T + b ----------------
__global__ void __launch_bounds__(256) preds_kernel(const float* __restrict__ woutw,
                                                    const float* __restrict__ woutb,
                                                    float* __restrict__ out) {
    int t = blockIdx.x, tid = threadIdx.x;
    int pair = tid >> 5, lane = tid & 31;
    if (pair >= 8) return;
    int b = pair >> 1, e = pair & 1;
    const float* hrow = g_hist + t * 1024 + b * 256;
    const float* wr = woutw + e * 256;
    float s = 0.f;
    for (int k = lane; k < 256; k += 32) s += hrow[k] * wr[k];
#pragma unroll
    for (int o = 16; o; o >>= 1) s += __shfl_xor_sync(0xffffffffu, s, o);
    if (lane == 0) out[(t * 4 + b) * 2 + e] = s + woutb[e];
}

// ---------------- launch ----------------
extern "C" void kernel_launch(void* const* d_in, const int* in_sizes, int n_in,
                              void* d_out, int out_size) {
    const float* cam    = (const float*)d_in[0];
    const float* convw  = (const float*)d_in[1];
    const float* convb  = (const float*)d_in[2];
    const float* gamma  = (const float*)d_in[3];
    const float* beta   = (const float*)d_in[4];
    const float* ihw    = (const float*)d_in[5];
    const float* ihb    = (const float*)d_in[6];
    const float* icw    = (const float*)d_in[7];
    const float* icb    = (const float*)d_in[8];
    const float* ww     = (const float*)d_in[9];
    const float* wb     = (const float*)d_in[10];
    const float* wattnw = (const float*)d_in[11];
    // d_in[12] = wattn_b : drops out of softmax/log_softmax (shift-invariant)
    const float* wih    = (const float*)d_in[13];
    const float* whh    = (const float*)d_in[14];
    const float* bih    = (const float*)d_in[15];
    const float* bhh    = (const float*)d_in[16];
    const float* woutw  = (const float*)d_in[17];
    const float* woutb  = (const float*)d_in[18];
    float* out = (float*)d_out;

    aprep_kernel<<<1152, 256>>>(convw);
    convmma_kernel<<<NF * 4, 256>>>(cam, convb);
    stats_kernel<<<ND, 256>>>(gamma, beta);
    attn_kernel<<<NF, 256>>>(wattnw, out);
    init_kernel<<<NB, 256>>>(ihw, ihb, icw, icb);
    weff_kernel<<<ND, 256>>>(wih, ww, whh);
    g1_kernel<<<NF, 1024>>>(wih, wb, bih, bhh);
    for (int t = 0; t < NT; t++)
        step_kernel<<<NB, 1024>>>(t);
    preds_kernel<<<NT, 256>>>(woutw, woutb, out);
}